// round 13
// baseline (speedup 1.0000x reference)
#include <cuda_runtime.h>
#include <cuda.h>
#include <cstdint>
#include <math.h>

#define KDIM   784
#define KPAD   800
#define SLABR  16            // rows per slab
#define TILE_K 32            // 128B per row per tile (SW128 box)
#define NT     25            // tiles per slab (zero-fill cols 784..799)
#define RING   16
#define TILE_B 2048          // 16 rows * 128B
#define BLOCKT 96            // warps 0-1 consumers (64), warp 2 lane 0 producer
#define NWORK  592           // 4 blocks/SM * 148 SMs -> single wave

// smem layout (bytes)
#define OFF_FULL  32768      // 16 full mbars
#define OFF_EMPTY 32896      // 16 empty mbars
#define OFF_W1    33024      // 900 float4 (interleaved r + r>>3)
#define OFF_SW    47424      // 240 floats
#define OFF_PREB  48384      // 64 float4
#define OFF_REC   49408      // int[4]  producer->consumer slab ids
#define OFF_BREC  49424      // int[4]  batch slab ids (epilogue)
#define OFF_PUB   49440      // int     published-slab counter
#define SMEM_BYTES 49456

__device__ int g_ctr;
__global__ void reset_ctr_kernel() { g_ctr = 0; }

__device__ __forceinline__ void mbar_init(unsigned a, unsigned c) {
    asm volatile("mbarrier.init.shared.b64 [%0], %1;" :: "r"(a), "r"(c) : "memory");
}
__device__ __forceinline__ void mbar_expect(unsigned a, unsigned tx) {
    asm volatile("mbarrier.arrive.expect_tx.shared.b64 _, [%0], %1;"
                 :: "r"(a), "r"(tx) : "memory");
}
__device__ __forceinline__ void mbar_arrive(unsigned a) {
    asm volatile("mbarrier.arrive.shared.b64 _, [%0];" :: "r"(a) : "memory");
}
__device__ __forceinline__ void mbar_wait(unsigned a, unsigned parity) {
    asm volatile(
        "{\n\t.reg .pred P;\n\t"
        "W_%=:\n\t"
        "mbarrier.try_wait.parity.acquire.cta.shared::cta.b64 P, [%0], %1, 0x989680;\n\t"
        "@P bra.uni D_%=;\n\t"
        "bra.uni W_%=;\n\t"
        "D_%=:\n\t}" :: "r"(a), "r"(parity) : "memory");
}
__device__ __forceinline__ void tma_2d(unsigned dst, const CUtensorMap* tm,
                                       int cx, int cy, unsigned mbar) {
    asm volatile(
        "cp.async.bulk.tensor.2d.shared::cta.global.tile.mbarrier::complete_tx::bytes "
        "[%0], [%1, {%2, %3}], [%4];"
        :: "r"(dst), "l"(tm), "r"(cx), "r"(cy), "r"(mbar) : "memory");
}

__global__ void __launch_bounds__(BLOCKT) qhybrid_kernel(
    const __grid_constant__ CUtensorMap tmap,
    const float* __restrict__ W1, const float* __restrict__ b1,
    const float* __restrict__ qw,
    const float* __restrict__ W2, const float* __restrict__ b2,
    const float* __restrict__ W3, const float* __restrict__ b3,
    float* __restrict__ out, int B, int nslab)
{
    extern __shared__ __align__(1024) char smem[];
    float*  w1s  = (float*)(smem + OFF_W1);
    float*  sw   = (float*)(smem + OFF_SW);
    float4* preb = (float4*)(smem + OFF_PREB);
    volatile int* rec  = (volatile int*)(smem + OFF_REC);
    int*    brec = (int*)(smem + OFF_BREC);
    volatile int* pub  = (volatile int*)(smem + OFF_PUB);

    const int tid = threadIdx.x;
    const unsigned smem_u = (unsigned)__cvta_generic_to_shared(smem);

    if (tid == 0) {
        #pragma unroll
        for (int i = 0; i < RING; i++) {
            mbar_init(smem_u + OFF_FULL + i * 8, 1);
            mbar_init(smem_u + OFF_EMPTY + i * 8, 64);
        }
        *pub = 0;
    }
    // W1 (interleaved, zero-pad 784..799) + small weights
    for (int r = tid; r < KPAD; r += BLOCKT) {
        float4 v = make_float4(0.f, 0.f, 0.f, 0.f);
        if (r < KDIM) v = __ldg((const float4*)W1 + r);
        ((float4*)w1s)[r + (r >> 3)] = v;
    }
    if (tid < 4)  sw[tid]       = b1[tid];
    if (tid < 8)  sw[4 + tid]   = qw[tid];
    for (int j = tid; j < 128; j += BLOCKT) sw[12 + j] = W2[j];
    if (tid < 32) sw[140 + tid] = b2[tid];
    if (tid < 64) sw[172 + tid] = W3[tid];
    if (tid < 2)  sw[236 + tid] = b3[tid];
    __syncthreads();

    // ================= producer (warp 2, lane 0) =================
    if (tid >= 64) {
        if (tid == 64) {
            asm volatile("fence.proxy.async.shared::cta;" ::: "memory");
            long g = 0;
            int  i = 0;
            int  s = atomicAdd(&g_ctr, 1);
            if (s >= nslab) s = -1;
            rec[0] = s;
            __threadfence_block();
            *pub = 1;
            while (s >= 0) {
                #pragma unroll 1
                for (int kt = 0; kt < NT; kt++) {
                    const int  slot = (int)(g & 15);
                    const long n    = g >> 4;
                    if (n >= 1)
                        mbar_wait(smem_u + OFF_EMPTY + slot * 8,
                                  (unsigned)((n - 1) & 1));
                    mbar_expect(smem_u + OFF_FULL + slot * 8, TILE_B);
                    tma_2d(smem_u + (unsigned)(slot * TILE_B), &tmap,
                           kt * TILE_K, s * SLABR,
                           smem_u + OFF_FULL + slot * 8);
                    g++;
                }
                i++;
                s = atomicAdd(&g_ctr, 1);
                if (s >= nslab) s = -1;
                rec[i & 3] = s;
                __threadfence_block();
                *pub = i + 1;
            }
        }
        return;   // warp 2 (incl. idle lanes) exits; no further block barriers
    }

    // ================= consumers (warps 0-1: 64 threads) =================
    const int row = tid >> 2;          // 0..15
    const int kq  = tid & 3;           // K-quarter
    const char* xrow = smem + row * 128;

    // epilogue as a macro over (pre, sample)
    #define EPILOGUE(PRE, SAMPLE) do {                                        \
        float _acc[4] = {(PRE).x, (PRE).y, (PRE).z, (PRE).w};                 \
        float _cq[4], _sq[4];                                                 \
        _Pragma("unroll")                                                     \
        for (int q = 0; q < 4; q++) {                                         \
            float ang = fmaxf(_acc[q] + sw[q], 0.f);                          \
            __sincosf(0.5f * ang, &_sq[q], &_cq[q]);                          \
        }                                                                     \
        float _re[16], _im[16];                                               \
        _Pragma("unroll")                                                     \
        for (int ii = 0; ii < 16; ii++) {                                     \
            float m = 1.f;                                                    \
            _Pragma("unroll")                                                 \
            for (int q = 0; q < 4; q++)                                       \
                m *= ((ii >> (3 - q)) & 1) ? _sq[q] : _cq[q];                 \
            int kk = __popc(ii) & 3;                                          \
            _re[ii] = (kk == 0) ? m : ((kk == 2) ? -m : 0.f);                 \
            _im[ii] = (kk == 1) ? -m : ((kk == 3) ? m : 0.f);                 \
        }                                                                     \
        _Pragma("unroll")                                                     \
        for (int l = 0; l < 2; l++) {                                         \
            _Pragma("unroll")                                                 \
            for (int q = 0; q < 4; q++) {                                     \
                float cg, sg;                                                 \
                __sincosf(0.5f * sw[4 + l * 4 + q], &sg, &cg);                \
                const int mask = 8 >> q;                                      \
                _Pragma("unroll")                                             \
                for (int ii = 0; ii < 16; ii++) {                             \
                    if (ii & mask) continue;                                  \
                    const int i1 = ii | mask;                                 \
                    float r0 = _re[ii], ii0 = _im[ii];                        \
                    float r1 = _re[i1], ii1 = _im[i1];                        \
                    _re[ii] = fmaf(cg, r0,  sg * ii1);                        \
                    _im[ii] = fmaf(cg, ii0, -sg * r1);                        \
                    _re[i1] = fmaf(cg, r1,  sg * ii0);                        \
                    _im[i1] = fmaf(cg, ii1, -sg * r0);                        \
                }                                                             \
            }                                                                 \
            _Pragma("unroll")                                                 \
            for (int q = 0; q < 4; q++) {                                     \
                const int cmask = 8 >> q;                                     \
                const int tmask = 8 >> ((q + 1) & 3);                         \
                _Pragma("unroll")                                             \
                for (int ii = 0; ii < 16; ii++) {                             \
                    if ((ii & cmask) && !(ii & tmask)) {                      \
                        const int jj = ii | tmask;                            \
                        float t = _re[ii]; _re[ii] = _re[jj]; _re[jj] = t;    \
                        t = _im[ii]; _im[ii] = _im[jj]; _im[jj] = t;          \
                    }                                                         \
                }                                                             \
            }                                                                 \
        }                                                                     \
        float _ez[4] = {0.f, 0.f, 0.f, 0.f};                                  \
        _Pragma("unroll")                                                     \
        for (int ii = 0; ii < 16; ii++) {                                     \
            float p = _re[ii] * _re[ii] + _im[ii] * _im[ii];                  \
            _Pragma("unroll")                                                 \
            for (int q = 0; q < 4; q++)                                       \
                _ez[q] += ((ii >> (3 - q)) & 1) ? -p : p;                     \
        }                                                                     \
        _Pragma("unroll")                                                     \
        for (int q = 0; q < 4; q++)                                           \
            if (!(_ez[q] == _ez[q])) _ez[q] = 0.f;                            \
        float l0 = sw[236], l1 = sw[237];                                     \
        _Pragma("unroll")                                                     \
        for (int j = 0; j < 32; j++) {                                        \
            float pj = sw[140 + j];                                           \
            _Pragma("unroll")                                                 \
            for (int q = 0; q < 4; q++)                                       \
                pj = fmaf(_ez[q], sw[12 + q * 32 + j], pj);                   \
            pj = fmaxf(pj, 0.f);                                              \
            l0 = fmaf(pj, sw[172 + j * 2],     l0);                           \
            l1 = fmaf(pj, sw[172 + j * 2 + 1], l1);                           \
        }                                                                     \
        float mx = fmaxf(l0, l1);                                             \
        float e0 = __expf(l0 - mx), e1 = __expf(l1 - mx);                     \
        float inv = 1.f / (e0 + e1);                                          \
        long _s = (SAMPLE);                                                   \
        if (_s < (long)B)                                                     \
            *(float2*)(out + _s * 2) = make_float2(e0 * inv, e1 * inv);       \
    } while (0)

    int nsl = 0;
    #pragma unroll 1
    for (int i = 0; ; i++) {
        while (*pub <= i) {}
        __threadfence_block();
        const int s = rec[i & 3];
        if (s < 0) { nsl = i; break; }
        if (tid == 0) brec[i & 3] = s;

        float a0 = 0.f, a1 = 0.f, a2 = 0.f, a3 = 0.f;
        #pragma unroll 1
        for (int kt = 0; kt < NT; kt++) {
            const long g    = (long)i * NT + kt;
            const int  slot = (int)(g & 15);
            mbar_wait(smem_u + OFF_FULL + slot * 8, (unsigned)((g >> 4) & 1));
            const char* xb = xrow + slot * TILE_B;
            #pragma unroll
            for (int c = 0; c < 2; c++) {
                const int u = kq * 2 + c;
                float4 xv = *(const float4*)(xb + ((u ^ (row & 7)) << 4));
                const float xa[4] = {xv.x, xv.y, xv.z, xv.w};
                #pragma unroll
                for (int j = 0; j < 4; j++) {
                    const int r = kt * TILE_K + u * 4 + j;
                    float4 w = ((const float4*)w1s)[r + (r >> 3)];
                    a0 = fmaf(xa[j], w.x, a0);
                    a1 = fmaf(xa[j], w.y, a1);
                    a2 = fmaf(xa[j], w.z, a2);
                    a3 = fmaf(xa[j], w.w, a3);
                }
            }
            mbar_arrive(smem_u + OFF_EMPTY + slot * 8);
        }
        // reduce over the 4 K-quarters (lanes row*4 + kq, within one warp)
        a0 += __shfl_xor_sync(0xFFFFFFFFu, a0, 1); a0 += __shfl_xor_sync(0xFFFFFFFFu, a0, 2);
        a1 += __shfl_xor_sync(0xFFFFFFFFu, a1, 1); a1 += __shfl_xor_sync(0xFFFFFFFFu, a1, 2);
        a2 += __shfl_xor_sync(0xFFFFFFFFu, a2, 1); a2 += __shfl_xor_sync(0xFFFFFFFFu, a2, 2);
        a3 += __shfl_xor_sync(0xFFFFFFFFu, a3, 1); a3 += __shfl_xor_sync(0xFFFFFFFFu, a3, 2);
        if (kq == 0) preb[(i & 3) * 16 + row] = make_float4(a0, a1, a2, a3);

        if ((i & 3) == 3) {   // batch of 4 slabs complete -> 64 epilogues
            asm volatile("bar.sync 1, 64;" ::: "memory");
            float4 pre = preb[tid];
            long sample = (long)brec[tid >> 4] * SLABR + (tid & 15);
            EPILOGUE(pre, sample);
            asm volatile("bar.sync 1, 64;" ::: "memory");
        }
    }
    // flush remainder slabs
    const int rem = nsl & 3;
    asm volatile("bar.sync 1, 64;" ::: "memory");
    if (tid < rem * 16) {
        float4 pre = preb[tid];
        long sample = (long)brec[tid >> 4] * SLABR + (tid & 15);
        EPILOGUE(pre, sample);
    }
}

typedef CUresult (*PFN_encodeTiled)(
    CUtensorMap*, CUtensorMapDataType, cuuint32_t, void*,
    const cuuint64_t*, const cuuint64_t*, const cuuint32_t*, const cuuint32_t*,
    CUtensorMapInterleave, CUtensorMapSwizzle, CUtensorMapL2promotion,
    CUtensorMapFloatOOBfill);

extern "C" void kernel_launch(void* const* d_in, const int* in_sizes, int n_in,
                              void* d_out, int out_size) {
    const float* x  = (const float*)d_in[0];
    const float* W1 = (const float*)d_in[1];
    const float* b1 = (const float*)d_in[2];
    const float* qw = (const float*)d_in[3];
    const float* W2 = (const float*)d_in[4];
    const float* b2 = (const float*)d_in[5];
    const float* W3 = (const float*)d_in[6];
    const float* b3 = (const float*)d_in[7];
    float* out = (float*)d_out;

    int B = in_sizes[0] / KDIM;
    int nslab = (B + SLABR - 1) / SLABR;

    PFN_encodeTiled encode = nullptr;
    cudaDriverEntryPointQueryResult qres;
    cudaGetDriverEntryPoint("cuTensorMapEncodeTiled", (void**)&encode,
                            cudaEnableDefault, &qres);
    CUtensorMap tmap;
    cuuint64_t dims[2]    = {(cuuint64_t)KDIM, (cuuint64_t)B};
    cuuint64_t strides[1] = {(cuuint64_t)KDIM * sizeof(float)};
    cuuint32_t box[2]     = {TILE_K, SLABR};
    cuuint32_t estr[2]    = {1, 1};
    encode(&tmap, CU_TENSOR_MAP_DATA_TYPE_FLOAT32, 2, (void*)x,
           dims, strides, box, estr,
           CU_TENSOR_MAP_INTERLEAVE_NONE, CU_TENSOR_MAP_SWIZZLE_128B,
           CU_TENSOR_MAP_L2_PROMOTION_L2_256B, CU_TENSOR_MAP_FLOAT_OOB_FILL_NONE);

    int grid = NWORK < nslab ? NWORK : nslab;
    cudaFuncSetAttribute(qhybrid_kernel,
                         cudaFuncAttributeMaxDynamicSharedMemorySize, SMEM_BYTES);
    reset_ctr_kernel<<<1, 1>>>();
    qhybrid_kernel<<<grid, BLOCKT, SMEM_BYTES>>>(tmap, W1, b1, qw, W2, b2, W3, b3,
                                                 out, B, nslab);
}

// round 14
// speedup vs baseline: 1.0040x; 1.0040x over previous
#include <cuda_runtime.h>
#include <cuda.h>
#include <cstdint>
#include <math.h>

#define KDIM   784
#define KPAD   800
#define TILE_K 32            // cols per tile (128B rows, SW128 box)
#define NT     25            // tiles per chunk (800 cols, zero-filled past 784)
#define RING   6
#define DEPTH  5             // tiles in flight
#define TILE_B 4096          // 32 rows * 128B
#define BLOCKT 64            // 32 samples x 2 K-halves
#define CHUNKR 32            // rows per stolen chunk

// smem layout (bytes)
#define OFF_MBAR  24576      // 6 mbars (48B)
#define OFF_W1    24624      // 900 float4 interleaved (14400B)
#define OFF_SW    39024      // 240 floats (960B)
#define OFF_CID   39984      // int[4] chunk ids
#define SMEM_BYTES 40000     // 5 blocks/SM

__device__ int g_ctr;
__global__ void reset_ctr_kernel() { g_ctr = 0; }

__device__ __forceinline__ void mbar_init(unsigned a, unsigned c) {
    asm volatile("mbarrier.init.shared.b64 [%0], %1;" :: "r"(a), "r"(c) : "memory");
}
__device__ __forceinline__ void mbar_expect(unsigned a, unsigned tx) {
    asm volatile("mbarrier.arrive.expect_tx.shared.b64 _, [%0], %1;"
                 :: "r"(a), "r"(tx) : "memory");
}
__device__ __forceinline__ void mbar_wait(unsigned a, unsigned parity) {
    asm volatile(
        "{\n\t.reg .pred P;\n\t"
        "W_%=:\n\t"
        "mbarrier.try_wait.parity.acquire.cta.shared::cta.b64 P, [%0], %1, 0x989680;\n\t"
        "@P bra.uni D_%=;\n\t"
        "bra.uni W_%=;\n\t"
        "D_%=:\n\t}" :: "r"(a), "r"(parity) : "memory");
}
__device__ __forceinline__ void tma_2d(unsigned dst, const CUtensorMap* tm,
                                       int cx, int cy, unsigned mbar) {
    asm volatile(
        "cp.async.bulk.tensor.2d.shared::cta.global.tile.mbarrier::complete_tx::bytes "
        "[%0], [%1, {%2, %3}], [%4];"
        :: "r"(dst), "l"(tm), "r"(cx), "r"(cy), "r"(mbar) : "memory");
}

__global__ void __launch_bounds__(BLOCKT) qhybrid_kernel(
    const __grid_constant__ CUtensorMap tmap,
    const float* __restrict__ W1, const float* __restrict__ b1,
    const float* __restrict__ qw,
    const float* __restrict__ W2, const float* __restrict__ b2,
    const float* __restrict__ W3, const float* __restrict__ b3,
    float* __restrict__ out, int B, int nchunk)
{
    extern __shared__ __align__(1024) char smem[];
    float* w1s = (float*)(smem + OFF_W1);
    float* sw  = (float*)(smem + OFF_SW);
    volatile int* cid = (volatile int*)(smem + OFF_CID);

    const int tid = threadIdx.x;
    const unsigned smem_u = (unsigned)__cvta_generic_to_shared(smem);
    const unsigned mbar0  = smem_u + OFF_MBAR;

    if (tid == 0) {
        #pragma unroll
        for (int i = 0; i < RING; i++) mbar_init(mbar0 + i * 8, 1);
    }
    // W1 interleaved (zero-pad rows 784..799) + small weights
    for (int r = tid; r < KPAD; r += BLOCKT) {
        float4 v = make_float4(0.f, 0.f, 0.f, 0.f);
        if (r < KDIM) v = __ldg((const float4*)W1 + r);
        ((float4*)w1s)[r + (r >> 3)] = v;
    }
    if (tid < 4)  sw[tid]       = b1[tid];
    if (tid < 8)  sw[4 + tid]   = qw[tid];
    for (int j = tid; j < 128; j += BLOCKT) sw[12 + j] = W2[j];
    if (tid < 32) sw[140 + tid] = b2[tid];
    if (tid < 64) sw[172 + tid] = W3[tid];
    if (tid < 2)  sw[236 + tid] = b3[tid];
    __syncthreads();

    int ic = -1;   // tid0: chunk id currently being issued
    if (tid == 0) {
        asm volatile("fence.proxy.async.shared::cta;" ::: "memory");
        int c0 = atomicAdd(&g_ctr, 1);
        if (c0 >= nchunk) c0 = -1;
        cid[0] = c0;
        ic = c0;
        if (c0 >= 0) {
            #pragma unroll
            for (int f = 0; f < DEPTH; f++) {
                mbar_expect(mbar0 + f * 8, TILE_B);
                tma_2d(smem_u + f * TILE_B, &tmap, f * TILE_K, c0 * CHUNKR,
                       mbar0 + f * 8);
            }
        }
    }
    __syncthreads();

    const int row = tid >> 1;          // 0..31 sample row
    const int kh  = tid & 1;           // K half
    const char* xrow = smem + row * 128;
    float a0 = 0.f, a1 = 0.f, a2 = 0.f, a3 = 0.f;
    int  ccur = 0;
    long t = 0;

    #pragma unroll 1
    for (;;) {
        const int kt = (int)(t % NT);
        if (kt == 0) {
            ccur = cid[(int)((t / NT) & 3)];
            if (ccur < 0) break;
            a0 = a1 = a2 = a3 = 0.f;
        }
        const int slot = (int)(t % RING);
        mbar_wait(mbar0 + (unsigned)(slot * 8), (unsigned)((t / RING) & 1));
        __syncthreads();   // tile t visible; slot (t+DEPTH)%RING free for reuse

        if (tid == 0) {
            const long f  = t + DEPTH;
            const int  fk = (int)(f % NT);
            if (fk == 0) {   // prefetch pointer crosses into a new chunk: steal it
                int cn = atomicAdd(&g_ctr, 1);
                if (cn >= nchunk) cn = -1;
                ic = cn;
                cid[(int)((f / NT) & 3)] = cn;
            }
            if (ic >= 0) {
                const int fs = (int)(f % RING);
                mbar_expect(mbar0 + fs * 8, TILE_B);
                tma_2d(smem_u + (unsigned)(fs * TILE_B), &tmap,
                       fk * TILE_K, ic * CHUNKR, mbar0 + fs * 8);
            }
        }

        // compute tile t: this thread's 16 cols (4 swizzled float4)
        const char* xb = xrow + slot * TILE_B;
        #pragma unroll
        for (int j = 0; j < 4; j++) {
            const int c = kh * 4 + j;
            float4 xv = *(const float4*)(xb + ((c ^ (row & 7)) << 4));
            const float xa[4] = {xv.x, xv.y, xv.z, xv.w};
            const int rbase = kt * TILE_K + kh * 16 + j * 4;
            #pragma unroll
            for (int jj = 0; jj < 4; jj++) {
                const int r = rbase + jj;
                float4 w = ((const float4*)w1s)[r + (r >> 3)];
                a0 = fmaf(xa[jj], w.x, a0);
                a1 = fmaf(xa[jj], w.y, a1);
                a2 = fmaf(xa[jj], w.z, a2);
                a3 = fmaf(xa[jj], w.w, a3);
            }
        }

        if (kt == NT - 1) {
            // combine the two K-halves (lane pairs 2r/2r+1)
            a0 += __shfl_xor_sync(0xFFFFFFFFu, a0, 1);
            a1 += __shfl_xor_sync(0xFFFFFFFFu, a1, 1);
            a2 += __shfl_xor_sync(0xFFFFFFFFu, a2, 1);
            a3 += __shfl_xor_sync(0xFFFFFFFFu, a3, 1);

            // ---- epilogue (all lanes compute; kh==0 stores) ----
            float acc[4] = {a0, a1, a2, a3};
            float cq[4], sq[4];
            #pragma unroll
            for (int q = 0; q < 4; q++) {
                float ang = fmaxf(acc[q] + sw[q], 0.f);
                __sincosf(0.5f * ang, &sq[q], &cq[q]);
            }
            float re[16], im[16];
            #pragma unroll
            for (int i = 0; i < 16; i++) {
                float m = 1.f;
                #pragma unroll
                for (int q = 0; q < 4; q++)
                    m *= ((i >> (3 - q)) & 1) ? sq[q] : cq[q];
                int k = __popc(i) & 3;
                re[i] = (k == 0) ? m : ((k == 2) ? -m : 0.f);
                im[i] = (k == 1) ? -m : ((k == 3) ? m : 0.f);
            }
            #pragma unroll
            for (int l = 0; l < 2; l++) {
                #pragma unroll
                for (int q = 0; q < 4; q++) {
                    float cg, sg;
                    __sincosf(0.5f * sw[4 + l * 4 + q], &sg, &cg);
                    const int mask = 8 >> q;
                    #pragma unroll
                    for (int i = 0; i < 16; i++) {
                        if (i & mask) continue;
                        const int i1 = i | mask;
                        float r0 = re[i], ii0 = im[i], r1 = re[i1], ii1 = im[i1];
                        re[i]  = fmaf(cg, r0,  sg * ii1);
                        im[i]  = fmaf(cg, ii0, -sg * r1);
                        re[i1] = fmaf(cg, r1,  sg * ii0);
                        im[i1] = fmaf(cg, ii1, -sg * r0);
                    }
                }
                #pragma unroll
                for (int q = 0; q < 4; q++) {
                    const int cmask = 8 >> q;
                    const int tmask = 8 >> ((q + 1) & 3);
                    #pragma unroll
                    for (int i = 0; i < 16; i++) {
                        if ((i & cmask) && !(i & tmask)) {
                            const int j = i | tmask;
                            float tt = re[i]; re[i] = re[j]; re[j] = tt;
                            tt = im[i]; im[i] = im[j]; im[j] = tt;
                        }
                    }
                }
            }
            float ez[4] = {0.f, 0.f, 0.f, 0.f};
            #pragma unroll
            for (int i = 0; i < 16; i++) {
                float p = re[i] * re[i] + im[i] * im[i];
                #pragma unroll
                for (int q = 0; q < 4; q++)
                    ez[q] += ((i >> (3 - q)) & 1) ? -p : p;
            }
            #pragma unroll
            for (int q = 0; q < 4; q++)
                if (!(ez[q] == ez[q])) ez[q] = 0.f;
            float l0 = sw[236], l1 = sw[237];
            #pragma unroll
            for (int j = 0; j < 32; j++) {
                float pj = sw[140 + j];
                #pragma unroll
                for (int q = 0; q < 4; q++)
                    pj = fmaf(ez[q], sw[12 + q * 32 + j], pj);
                pj = fmaxf(pj, 0.f);
                l0 = fmaf(pj, sw[172 + j * 2],     l0);
                l1 = fmaf(pj, sw[172 + j * 2 + 1], l1);
            }
            float mx = fmaxf(l0, l1);
            float e0 = __expf(l0 - mx), e1 = __expf(l1 - mx);
            float inv = 1.f / (e0 + e1);
            long sample = (long)ccur * CHUNKR + row;
            if (kh == 0 && sample < (long)B)
                *(float2*)(out + sample * 2) = make_float2(e0 * inv, e1 * inv);
        }
        t++;
    }
}

typedef CUresult (*PFN_encodeTiled)(
    CUtensorMap*, CUtensorMapDataType, cuuint32_t, void*,
    const cuuint64_t*, const cuuint64_t*, const cuuint32_t*, const cuuint32_t*,
    CUtensorMapInterleave, CUtensorMapSwizzle, CUtensorMapL2promotion,
    CUtensorMapFloatOOBfill);

extern "C" void kernel_launch(void* const* d_in, const int* in_sizes, int n_in,
                              void* d_out, int out_size) {
    const float* x  = (const float*)d_in[0];
    const float* W1 = (const float*)d_in[1];
    const float* b1 = (const float*)d_in[2];
    const float* qw = (const float*)d_in[3];
    const float* W2 = (const float*)d_in[4];
    const float* b2 = (const float*)d_in[5];
    const float* W3 = (const float*)d_in[6];
    const float* b3 = (const float*)d_in[7];
    float* out = (float*)d_out;

    int B = in_sizes[0] / KDIM;
    int nchunk = (B + CHUNKR - 1) / CHUNKR;

    PFN_encodeTiled encode = nullptr;
    cudaDriverEntryPointQueryResult qres;
    cudaGetDriverEntryPoint("cuTensorMapEncodeTiled", (void**)&encode,
                            cudaEnableDefault, &qres);
    CUtensorMap tmap;
    cuuint64_t dims[2]    = {(cuuint64_t)KDIM, (cuuint64_t)B};
    cuuint64_t strides[1] = {(cuuint64_t)KDIM * sizeof(float)};
    cuuint32_t box[2]     = {TILE_K, CHUNKR};
    cuuint32_t estr[2]    = {1, 1};
    encode(&tmap, CU_TENSOR_MAP_DATA_TYPE_FLOAT32, 2, (void*)x,
           dims, strides, box, estr,
           CU_TENSOR_MAP_INTERLEAVE_NONE, CU_TENSOR_MAP_SWIZZLE_128B,
           CU_TENSOR_MAP_L2_PROMOTION_L2_256B, CU_TENSOR_MAP_FLOAT_OOB_FILL_NONE);

    int grid = 760;                       // 5 blocks/SM on 152 SMs; stealing balances
    if (grid > nchunk) grid = nchunk;
    cudaFuncSetAttribute(qhybrid_kernel,
                         cudaFuncAttributeMaxDynamicSharedMemorySize, SMEM_BYTES);
    reset_ctr_kernel<<<1, 1>>>();
    qhybrid_kernel<<<grid, BLOCKT, SMEM_BYTES>>>(tmap, W1, b1, qw, W2, b2, W3, b3,
                                                 out, B, nchunk);
}

// round 15
// speedup vs baseline: 1.1543x; 1.1496x over previous
#include <cuda_runtime.h>
#include <cuda.h>
#include <cstdint>
#include <math.h>

#define BLOCKT  64            // 64 threads = 64 samples per block
#define KDIM    784
#define KPAD    800
#define TILE_K  32            // 32 cols * 4B = 128B rows (SW128 box)
#define NT      25            // 25*32 = 800 (TMA zero-fills cols >= 784)
#define RING    5
#define DEPTH   4             // tiles in flight
#define TILE_B  8192          // 64 rows * 128B
// smem bytes: xs 5*8192=40960 | mbars @40960 (40B) | w1s @41024 (12800B) | sw @53824 (960B)
#define OFF_MBAR 40960
#define OFF_W1   41024
#define OFF_SW   53824
#define SMEM_BYTES 54784      // 4 blocks/SM

__device__ __forceinline__ void mbar_init1(unsigned addr) {
    asm volatile("mbarrier.init.shared.b64 [%0], 1;" :: "r"(addr) : "memory");
}
__device__ __forceinline__ void mbar_expect(unsigned addr, unsigned tx) {
    asm volatile("mbarrier.arrive.expect_tx.shared.b64 _, [%0], %1;"
                 :: "r"(addr), "r"(tx) : "memory");
}
__device__ __forceinline__ void mbar_wait(unsigned addr, unsigned parity) {
    asm volatile(
        "{\n\t.reg .pred P;\n\t"
        "WAIT_%=:\n\t"
        "mbarrier.try_wait.parity.acquire.cta.shared::cta.b64 P, [%0], %1, 0x989680;\n\t"
        "@P bra.uni DONE_%=;\n\t"
        "bra.uni WAIT_%=;\n\t"
        "DONE_%=:\n\t}"
        :: "r"(addr), "r"(parity) : "memory");
}
__device__ __forceinline__ void tma_2d(unsigned dst, const CUtensorMap* tm,
                                       int cx, int cy, unsigned mbar) {
    asm volatile(
        "cp.async.bulk.tensor.2d.shared::cta.global.tile.mbarrier::complete_tx::bytes "
        "[%0], [%1, {%2, %3}], [%4];"
        :: "r"(dst), "l"(tm), "r"(cx), "r"(cy), "r"(mbar) : "memory");
}

__global__ void __launch_bounds__(BLOCKT) qhybrid_kernel(
    const __grid_constant__ CUtensorMap tmap,
    const float* __restrict__ W1, const float* __restrict__ b1,
    const float* __restrict__ qw,
    const float* __restrict__ W2, const float* __restrict__ b2,
    const float* __restrict__ W3, const float* __restrict__ b3,
    float* __restrict__ out, int B)
{
    extern __shared__ __align__(1024) char smem[];
    char*  xs  = smem;                          // [5][64 rows][128B] swizzled
    float* w1s = (float*)(smem + OFF_W1);       // [800][4]
    float* sw  = (float*)(smem + OFF_SW);       // small weights

    const int tid = threadIdx.x;
    const unsigned smem_u = (unsigned)__cvta_generic_to_shared(smem);
    const unsigned mbar0  = smem_u + OFF_MBAR;  // 5 mbars * 8B

    // ---- tid 0: init ring mbarriers, kick off DEPTH tiles immediately ----
    if (tid == 0) {
        #pragma unroll
        for (int i = 0; i < RING; i++) mbar_init1(mbar0 + i * 8);
        asm volatile("fence.proxy.async.shared::cta;" ::: "memory");
        const int rowbase = blockIdx.x * BLOCKT;
        #pragma unroll
        for (int kt = 0; kt < DEPTH; kt++) {
            mbar_expect(mbar0 + kt * 8, TILE_B);
            tma_2d(smem_u + kt * TILE_B, &tmap, kt * TILE_K, rowbase, mbar0 + kt * 8);
        }
    }

    // ---- preload W1 (zero-padded rows 784..799) + small weights ----
    for (int r = tid; r < KPAD; r += BLOCKT) {
        float4 v = make_float4(0.f, 0.f, 0.f, 0.f);
        if (r < KDIM) v = __ldg((const float4*)W1 + r);
        ((float4*)w1s)[r] = v;
    }
    // b1@0(4) qw@4(8) W2@12(128) b2@140(32) W3@172(64) b3@236(2)
    if (tid < 4)  sw[tid]      = b1[tid];
    if (tid < 8)  sw[4 + tid]  = qw[tid];
    for (int j = tid; j < 128; j += BLOCKT) sw[12 + j] = W2[j];
    if (tid < 32) sw[140 + tid] = b2[tid];
    for (int j = tid; j < 64; j += BLOCKT)  sw[172 + j] = W3[j];
    if (tid < 2)  sw[236 + tid] = b3[tid];
    __syncthreads();    // publish w1s/sw; orders mbar init for all threads

    float acc[4] = {0.f, 0.f, 0.f, 0.f};
    const int rsw = (tid & 7);          // swizzle key for this thread's row
    char* xrow_base = xs + tid * 128;   // + slot*TILE_B

    // ---- GEMM mainloop: TMA ring, one barrier per iter ----
    #pragma unroll 1
    for (int kt = 0; kt < NT; kt++) {
        const int slot = kt % RING;
        mbar_wait(mbar0 + (unsigned)(slot * 8), (unsigned)((kt / RING) & 1));
        __syncthreads();   // all warps done with slot reads from iter kt-1; tile kt visible

        if (tid == 0) {
            const int kp = kt + DEPTH;
            if (kp < NT) {
                const int fs = kp % RING;      // == slot freed by iter kt-1
                const unsigned mb = mbar0 + (unsigned)(fs * 8);
                mbar_expect(mb, TILE_B);
                tma_2d(smem_u + (unsigned)(fs * TILE_B), &tmap,
                       kp * TILE_K, blockIdx.x * BLOCKT, mb);
            }
        }

        // compute tile kt: 8 swizzled float4 chunks of this thread's row
        const char* xr = xrow_base + slot * TILE_B;
        const float* wb = w1s + kt * TILE_K * 4;
        #pragma unroll
        for (int j = 0; j < 8; j++) {
            float4 xv = *(const float4*)(xr + ((j ^ rsw) << 4));
            const float* wp = wb + j * 16;
            float4 wa = *(const float4*)(wp);
            float4 w2 = *(const float4*)(wp + 4);
            float4 w3 = *(const float4*)(wp + 8);
            float4 w4 = *(const float4*)(wp + 12);
            acc[0]=fmaf(xv.x,wa.x,acc[0]); acc[1]=fmaf(xv.x,wa.y,acc[1]);
            acc[2]=fmaf(xv.x,wa.z,acc[2]); acc[3]=fmaf(xv.x,wa.w,acc[3]);
            acc[0]=fmaf(xv.y,w2.x,acc[0]); acc[1]=fmaf(xv.y,w2.y,acc[1]);
            acc[2]=fmaf(xv.y,w2.z,acc[2]); acc[3]=fmaf(xv.y,w2.w,acc[3]);
            acc[0]=fmaf(xv.z,w3.x,acc[0]); acc[1]=fmaf(xv.z,w3.y,acc[1]);
            acc[2]=fmaf(xv.z,w3.z,acc[2]); acc[3]=fmaf(xv.z,w3.w,acc[3]);
            acc[0]=fmaf(xv.w,w4.x,acc[0]); acc[1]=fmaf(xv.w,w4.y,acc[1]);
            acc[2]=fmaf(xv.w,w4.z,acc[2]); acc[3]=fmaf(xv.w,w4.w,acc[3]);
        }
    }

    // ---- angles = relu(pre + b1) ----
    float cq[4], sq[4];
    #pragma unroll
    for (int q = 0; q < 4; q++) {
        float ang = fmaxf(acc[q] + sw[q], 0.f);
        __sincosf(0.5f * ang, &sq[q], &cq[q]);
    }

    // ---- 4-qubit statevector in registers ----
    float re[16], im[16];
    #pragma unroll
    for (int i = 0; i < 16; i++) {
        float m = 1.f;
        #pragma unroll
        for (int q = 0; q < 4; q++) m *= ((i >> (3 - q)) & 1) ? sq[q] : cq[q];
        int k = __popc(i) & 3;  // phase (-i)^k
        re[i] = (k == 0) ? m : ((k == 2) ? -m : 0.f);
        im[i] = (k == 1) ? -m : ((k == 3) ? m : 0.f);
    }

    // ---- BasicEntanglerLayers: RX(w[l,q]) then CNOT ring ----
    #pragma unroll
    for (int l = 0; l < 2; l++) {
        #pragma unroll
        for (int q = 0; q < 4; q++) {
            float cg, sg;
            __sincosf(0.5f * sw[4 + l * 4 + q], &sg, &cg);
            const int mask = 8 >> q;
            #pragma unroll
            for (int i = 0; i < 16; i++) {
                if (i & mask) continue;
                const int i1 = i | mask;
                float r0 = re[i], ii0 = im[i], r1 = re[i1], ii1 = im[i1];
                re[i]  = fmaf(cg, r0,  sg * ii1);
                im[i]  = fmaf(cg, ii0, -sg * r1);
                re[i1] = fmaf(cg, r1,  sg * ii0);
                im[i1] = fmaf(cg, ii1, -sg * r0);
            }
        }
        #pragma unroll
        for (int q = 0; q < 4; q++) {
            const int cmask = 8 >> q;
            const int tmask = 8 >> ((q + 1) & 3);
            #pragma unroll
            for (int i = 0; i < 16; i++) {
                if ((i & cmask) && !(i & tmask)) {
                    const int j = i | tmask;
                    float t = re[i]; re[i] = re[j]; re[j] = t;
                    t = im[i]; im[i] = im[j]; im[j] = t;
                }
            }
        }
    }

    // ---- <Z_q> expectation values ----
    float ez[4] = {0.f, 0.f, 0.f, 0.f};
    #pragma unroll
    for (int i = 0; i < 16; i++) {
        float p = re[i] * re[i] + im[i] * im[i];
        #pragma unroll
        for (int q = 0; q < 4; q++)
            ez[q] += ((i >> (3 - q)) & 1) ? -p : p;
    }
    #pragma unroll
    for (int q = 0; q < 4; q++)
        if (!(ez[q] == ez[q])) ez[q] = 0.f;  // NaN -> 0 (matches reference)

    // ---- post = relu(ez@W2 + b2); logits = post@W3 + b3; softmax ----
    float l0 = sw[236], l1 = sw[237];
    #pragma unroll
    for (int j = 0; j < 32; j++) {
        float pj = sw[140 + j];
        #pragma unroll
        for (int q = 0; q < 4; q++)
            pj = fmaf(ez[q], sw[12 + q * 32 + j], pj);
        pj = fmaxf(pj, 0.f);
        l0 = fmaf(pj, sw[172 + j * 2],     l0);
        l1 = fmaf(pj, sw[172 + j * 2 + 1], l1);
    }
    float mx = fmaxf(l0, l1);
    float e0 = __expf(l0 - mx);
    float e1 = __expf(l1 - mx);
    float inv = 1.f / (e0 + e1);

    long sg = (long)blockIdx.x * BLOCKT + tid;
    if (sg < (long)B) {
        float2 o = make_float2(e0 * inv, e1 * inv);
        *(float2*)(out + sg * 2) = o;
    }
}

typedef CUresult (*PFN_encodeTiled)(
    CUtensorMap*, CUtensorMapDataType, cuuint32_t, void*,
    const cuuint64_t*, const cuuint64_t*, const cuuint32_t*, const cuuint32_t*,
    CUtensorMapInterleave, CUtensorMapSwizzle, CUtensorMapL2promotion,
    CUtensorMapFloatOOBfill);

extern "C" void kernel_launch(void* const* d_in, const int* in_sizes, int n_in,
                              void* d_out, int out_size) {
    const float* x  = (const float*)d_in[0];
    const float* W1 = (const float*)d_in[1];
    const float* b1 = (const float*)d_in[2];
    const float* qw = (const float*)d_in[3];
    const float* W2 = (const float*)d_in[4];
    const float* b2 = (const float*)d_in[5];
    const float* W3 = (const float*)d_in[6];
    const float* b3 = (const float*)d_in[7];
    float* out = (float*)d_out;

    int B = in_sizes[0] / KDIM;

    // Tensor map for x: [B rows, 784 cols] fp32, box [32, 64], SW128, L2 256B.
    PFN_encodeTiled encode = nullptr;
    cudaDriverEntryPointQueryResult qres;
    cudaGetDriverEntryPoint("cuTensorMapEncodeTiled", (void**)&encode,
                            cudaEnableDefault, &qres);
    CUtensorMap tmap;
    cuuint64_t dims[2]    = {(cuuint64_t)KDIM, (cuuint64_t)B};
    cuuint64_t strides[1] = {(cuuint64_t)KDIM * sizeof(float)};
    cuuint32_t box[2]     = {TILE_K, BLOCKT};
    cuuint32_t estr[2]    = {1, 1};
    encode(&tmap, CU_TENSOR_MAP_DATA_TYPE_FLOAT32, 2, (void*)x,
           dims, strides, box, estr,
           CU_TENSOR_MAP_INTERLEAVE_NONE, CU_TENSOR_MAP_SWIZZLE_128B,
           CU_TENSOR_MAP_L2_PROMOTION_L2_256B, CU_TENSOR_MAP_FLOAT_OOB_FILL_NONE);

    int grid = (B + BLOCKT - 1) / BLOCKT;           // 1024 blocks
    cudaFuncSetAttribute(qhybrid_kernel,
                         cudaFuncAttributeMaxDynamicSharedMemorySize, SMEM_BYTES);
    qhybrid_kernel<<<grid, BLOCKT, SMEM_BYTES>>>(tmap, W1, b1, qw, W2, b2, W3, b3, out, B);
}